// round 9
// baseline (speedup 1.0000x reference)
#include <cuda_runtime.h>
#include <cuda_bf16.h>
#include <cuda_fp8.h>
#include <cstdint>

// NT-Xent fused: N=4096, Z=128, T=0.5
#define TWO_N 8192
#define ZD 128
#define INV_T 2.0f
// exp(sim/T) = 2^(sim*INV_T*log2(e)). Rows stored in e4m3 scaled by
// 16*sqrt(INV_T*log2(e)) so acc = 256 * sim * 2.88539; ex2 arg = acc * 2^-8.
#define ROW_SCALE 27.17829704230117f     // 16 * sqrt(2 * log2(e))
#define ACC_TO_EX2 0.00390625f           // 2^-8
#define LN2F 0.6931471805599453f

#define BM 128
#define BN 128
#define ROW_TILES (TWO_N / BM)                       // 64
#define NUM_TILES (ROW_TILES * (ROW_TILES + 1) / 2)  // 2080 (upper triangle)
#define NUM_CTAS 304                     // persistent: 2 per SM x 152 SMs
#define STRIDEB 144                      // bytes per smem row (128 + 16 pad)
#define TILE_BYTES (BM * STRIDEB)        // 18432
#define SMEM_SZ (3 * TILE_BYTES)         // A + B0 + B1 = 55296

// Scratch (device globals — no allocation allowed)
__device__ uint8_t g_nrep_fp8[TWO_N * ZD];
__device__ float   g_rowsum  [TWO_N];
__device__ float   g_pos     [TWO_N];
__device__ unsigned int g_ticket;

// ---------------------------------------------------------------------------
// Kernel 1: normalize both rows of each positive pair (j, j+N) in one block;
// emit scaled e4m3 rows, fp32 positives, zero rowsums. 4096 blocks x 128.
// ---------------------------------------------------------------------------
__global__ void normalize_pos_kernel(const float* __restrict__ z1,
                                     const float* __restrict__ z2) {
    int j = blockIdx.x;                      // 0..4095
    int t = threadIdx.x;
    float v = z1[(size_t)j * ZD + t];
    float p = z2[(size_t)j * ZD + t];
    float s0 = v * v, s1 = p * p, s2 = v * p;
    #pragma unroll
    for (int o = 16; o > 0; o >>= 1) {
        s0 += __shfl_xor_sync(0xFFFFFFFFu, s0, o);
        s1 += __shfl_xor_sync(0xFFFFFFFFu, s1, o);
        s2 += __shfl_xor_sync(0xFFFFFFFFu, s2, o);
    }
    __shared__ float ws[4][3];
    int lane = t & 31, wid = t >> 5;
    if (lane == 0) { ws[wid][0] = s0; ws[wid][1] = s1; ws[wid][2] = s2; }
    __syncthreads();
    float n0 = ws[0][0] + ws[1][0] + ws[2][0] + ws[3][0];
    float n1 = ws[0][1] + ws[1][1] + ws[2][1] + ws[3][1];
    float dp = ws[0][2] + ws[1][2] + ws[2][2] + ws[3][2];
    float invA = 1.0f / fmaxf(sqrtf(n0), 1e-8f);
    float invB = 1.0f / fmaxf(sqrtf(n1), 1e-8f);
    g_nrep_fp8[(size_t)j * ZD + t] =
        (uint8_t)__nv_cvt_float_to_fp8(v * (invA * ROW_SCALE), __NV_SATFINITE, __NV_E4M3);
    g_nrep_fp8[(size_t)(j + TWO_N/2) * ZD + t] =
        (uint8_t)__nv_cvt_float_to_fp8(p * (invB * ROW_SCALE), __NV_SATFINITE, __NV_E4M3);
    if (t == 0) {
        float pos = dp * invA * invB;
        g_pos[j] = pos;
        g_pos[j + TWO_N/2] = pos;
        g_rowsum[j] = 0.0f;
        g_rowsum[j + TWO_N/2] = 0.0f;
        if (j == 0) g_ticket = 0u;
    }
}

// ---------------------------------------------------------------------------
// cp.async a full 128x128 fp8 tile (row strip rowBase) into padded smem
// ---------------------------------------------------------------------------
__device__ __forceinline__ void load_tile(uint8_t* dst, int rowBase, int tid) {
    #pragma unroll
    for (int it = 0; it < 2; it++) {
        int i2 = it * 512 + tid;          // 1024 16B-chunks per tile
        int rr = i2 >> 3, c = i2 & 7;
        uint32_t d = (uint32_t)__cvta_generic_to_shared(dst + rr * STRIDEB + c * 16);
        const void* g = g_nrep_fp8 + (size_t)(rowBase + rr) * ZD + c * 16;
        asm volatile("cp.async.cg.shared.global [%0], [%1], 16;" :: "r"(d), "l"(g));
    }
}

// ---------------------------------------------------------------------------
// Epilogue (templated on DIAG): ex = ex2(acc * 2^-8), optional self-diag
// mask; row sums always, column sums (symmetry) for off-diag tiles.
// ---------------------------------------------------------------------------
template<bool DIAG>
__device__ __forceinline__ void epilogue(float (&acc)[2][4][4], int rowBase,
                                         int colBase, int wm, int wn, int lane) {
    int g = lane >> 2, t = lane & 3;

    float colacc[8];
    #pragma unroll
    for (int c = 0; c < 8; c++) colacc[c] = 0.0f;

    #pragma unroll
    for (int mt = 0; mt < 2; mt++) {
        #pragma unroll
        for (int half = 0; half < 2; half++) {
            int i = rowBase + wm * 32 + mt * 16 + half * 8 + g;
            float s = 0.0f;
            #pragma unroll
            for (int nt = 0; nt < 4; nt++) {
                #pragma unroll
                for (int e = 0; e < 2; e++) {
                    float ex;
                    asm("ex2.approx.f32 %0, %1;" : "=f"(ex)
                        : "f"(acc[mt][nt][half * 2 + e] * ACC_TO_EX2));
                    if (DIAG) {
                        int j = colBase + wn * 32 + t * 2 + nt * 8 + e;
                        if (i == j) ex = 0.0f;
                    }
                    s += ex;
                    colacc[nt * 2 + e] += ex;
                }
            }
            s += __shfl_xor_sync(0xFFFFFFFFu, s, 1);
            s += __shfl_xor_sync(0xFFFFFFFFu, s, 2);
            if (t == 0) atomicAdd(&g_rowsum[i], s);
        }
    }

    if (!DIAG) {
        #pragma unroll
        for (int c = 0; c < 8; c++) {
            float v = colacc[c];
            v += __shfl_xor_sync(0xFFFFFFFFu, v, 4);
            v += __shfl_xor_sync(0xFFFFFFFFu, v, 8);
            v += __shfl_xor_sync(0xFFFFFFFFu, v, 16);
            colacc[c] = v;
        }
        if (g == 0) {
            int jbase = colBase + wn * 32 + t * 2;
            #pragma unroll
            for (int c = 0; c < 8; c++) {
                int j = jbase + (c >> 1) * 8 + (c & 1);
                atomicAdd(&g_rowsum[j], colacc[c]);
            }
        }
    }
}

// ---------------------------------------------------------------------------
// Kernel 2: PERSISTENT fused sim GEMM in e4m3 (mma.sync.m16n8k32).
// 304 CTAs own contiguous chunks of the row-major upper triangle; B
// double-buffered via cp.async; A reloaded on row transitions only.
// 512 threads = 16 warps (4m x 4n), 32x32 warp tile.
// ---------------------------------------------------------------------------
__global__ void __launch_bounds__(512, 2) simgemm_kernel(float* __restrict__ out) {
    extern __shared__ uint8_t smem[];
    uint8_t* sA = smem;
    uint8_t* sB = smem + TILE_BYTES;            // B0; B1 at +TILE_BYTES

    int tid = threadIdx.x;
    int wid = tid >> 5, lane = tid & 31;

    // Contiguous chunk of the row-major triangle
    const int base = NUM_TILES / NUM_CTAS;      // 6
    const int rem  = NUM_TILES % NUM_CTAS;      // 256
    int bidx = blockIdx.x;
    int start = bidx * base + (bidx < rem ? bidx : rem);
    int count = base + (bidx < rem ? 1 : 0);

    // Decode (ty, tx) for start (row ty holds tiles tx in [ty, 64))
    int ty = 0, f = 0;
    while (f + (ROW_TILES - ty) <= start) { f += ROW_TILES - ty; ty++; }
    int tx = ty + (start - f);

    // Initial loads: A(ty) + B(tx) as one group
    load_tile(sA, ty * BM, tid);
    load_tile(sB, tx * BN, tid);
    asm volatile("cp.async.commit_group;" ::: "memory");

    int wm = wid & 3;        // warp row (4)
    int wn = wid >> 2;       // warp col (4)

    // ldmatrix base addresses (per lane), byte offsets; k advances 32B/step
    uint32_t aAddr[2];
    #pragma unroll
    for (int mt = 0; mt < 2; mt++) {
        int row = wm * 32 + mt * 16 + (lane & 15);
        aAddr[mt] = (uint32_t)__cvta_generic_to_shared(
            sA + row * STRIDEB + (lane >> 4) * 16);
    }
    uint32_t bAddr[2];
    #pragma unroll
    for (int ntp = 0; ntp < 2; ntp++) {
        int n = wn * 32 + ntp * 16 + ((lane >> 4) & 1) * 8 + (lane & 7);
        bAddr[ntp] = (uint32_t)__cvta_generic_to_shared(
            sB + n * STRIDEB + ((lane >> 3) & 1) * 16);
    }

    #pragma unroll 1
    for (int t = 0; t < count; t++) {
        uint32_t bOff = (uint32_t)(t & 1) * TILE_BYTES;
        int nty = ty, ntx = tx + 1;
        if (ntx == ROW_TILES) { nty = ty + 1; ntx = nty; }
        bool more = (t + 1 < count);

        // Wait for this tile's data (prefetched last iteration -> nearly free)
        asm volatile("cp.async.wait_group 0;" ::: "memory");
        __syncthreads();

        // Prefetch next tile's B into the alternate buffer; overlaps mainloop
        if (more) {
            load_tile(sB + ((t + 1) & 1) * TILE_BYTES, ntx * BN, tid);
            asm volatile("cp.async.commit_group;" ::: "memory");
        }

        float acc[2][4][4];
        #pragma unroll
        for (int mt = 0; mt < 2; mt++)
            #pragma unroll
            for (int nt = 0; nt < 4; nt++)
                #pragma unroll
                for (int e = 0; e < 4; e++) acc[mt][nt][e] = 0.0f;

        // ---- Mainloop: 4 k-steps of k32 (e4m3)
        #pragma unroll
        for (int ks = 0; ks < 4; ks++) {
            uint32_t a[2][4];
            #pragma unroll
            for (int mt = 0; mt < 2; mt++)
                asm volatile("ldmatrix.sync.aligned.m8n8.x4.shared.b16 {%0,%1,%2,%3}, [%4];"
                    : "=r"(a[mt][0]), "=r"(a[mt][1]), "=r"(a[mt][2]), "=r"(a[mt][3])
                    : "r"(aAddr[mt] + ks * 32));
            uint32_t b[4][2];
            #pragma unroll
            for (int ntp = 0; ntp < 2; ntp++)
                asm volatile("ldmatrix.sync.aligned.m8n8.x4.shared.b16 {%0,%1,%2,%3}, [%4];"
                    : "=r"(b[2*ntp][0]), "=r"(b[2*ntp][1]),
                      "=r"(b[2*ntp+1][0]), "=r"(b[2*ntp+1][1])
                    : "r"(bAddr[ntp] + bOff + ks * 32));
            #pragma unroll
            for (int mt = 0; mt < 2; mt++)
                #pragma unroll
                for (int nt = 0; nt < 4; nt++)
                    asm volatile(
                        "mma.sync.aligned.m16n8k32.row.col.f32.e4m3.e4m3.f32 "
                        "{%0,%1,%2,%3}, {%4,%5,%6,%7}, {%8,%9}, {%0,%1,%2,%3};"
                        : "+f"(acc[mt][nt][0]), "+f"(acc[mt][nt][1]),
                          "+f"(acc[mt][nt][2]), "+f"(acc[mt][nt][3])
                        : "r"(a[mt][0]), "r"(a[mt][1]), "r"(a[mt][2]), "r"(a[mt][3]),
                          "r"(b[nt][0]), "r"(b[nt][1]));
        }

        if (tx == ty) epilogue<true >(acc, ty * BM, tx * BN, wm, wn, lane);
        else          epilogue<false>(acc, ty * BM, tx * BN, wm, wn, lane);

        // Row transition: reload A (rare; bufA reuse needs all warps done)
        if (more && nty != ty) {
            __syncthreads();
            load_tile(sA, nty * BM, tid);
            asm volatile("cp.async.commit_group;" ::: "memory");
        }
        ty = nty; tx = ntx;
    }

    // ---- Ticket: last CTA computes the scalar loss (fast log2)
    __shared__ bool is_last;
    __syncthreads();
    if (tid == 0) {
        __threadfence();
        unsigned int tk = atomicInc(&g_ticket, 0xFFFFFFFFu);
        is_last = (tk == (unsigned int)(gridDim.x - 1));
    }
    __syncthreads();
    if (is_last) {
        __threadfence();
        float acc2 = 0.0f;
        #pragma unroll 4
        for (int i = tid; i < TWO_N; i += 512)
            acc2 += __log2f(__ldcg(&g_rowsum[i])) * LN2F - g_pos[i] * INV_T;
        #pragma unroll
        for (int o = 16; o > 0; o >>= 1)
            acc2 += __shfl_xor_sync(0xFFFFFFFFu, acc2, o);
        __shared__ float sred[16];
        if ((tid & 31) == 0) sred[tid >> 5] = acc2;
        __syncthreads();
        if (tid == 0) {
            float tot = 0.0f;
            #pragma unroll
            for (int w = 0; w < 16; w++) tot += sred[w];
            out[0] = tot * (1.0f / (float)TWO_N);
        }
    }
}

// ---------------------------------------------------------------------------
extern "C" void kernel_launch(void* const* d_in, const int* in_sizes, int n_in,
                              void* d_out, int out_size) {
    const float* z1 = (const float*)d_in[0];
    const float* z2 = (const float*)d_in[1];

    cudaFuncSetAttribute(simgemm_kernel,
                         cudaFuncAttributeMaxDynamicSharedMemorySize, SMEM_SZ);

    normalize_pos_kernel<<<TWO_N / 2, 128>>>(z1, z2);
    simgemm_kernel<<<NUM_CTAS, 512, SMEM_SZ>>>((float*)d_out);
}

// round 10
// speedup vs baseline: 1.1412x; 1.1412x over previous
#include <cuda_runtime.h>
#include <cuda_bf16.h>
#include <cstdint>

// NT-Xent fused: N=4096, Z=128, T=0.5
#define TWO_N 8192
#define ZD 128
#define INV_T 2.0f
// exp(sim/T) = 2^(sim * INV_T * log2(e)); fold sqrt of the scale into each
// stored bf16 row so the MMA accumulator is directly the ex2 argument.
#define SQRT_EXP_SCALE 1.6986435651438231f   // sqrt(2 * log2(e))
#define LN2F 0.6931471805599453f

#define BM 128
#define BN 128
#define ROW_TILES (TWO_N / BM)                       // 64
#define NUM_TILES (ROW_TILES * (ROW_TILES + 1) / 2)  // 2080 (upper triangle)
#define NUM_CTAS 304                     // persistent: 2 per SM x 152 SMs
#define STRIDE 136                       // bf16 elems per smem row (128 + 8 pad)
#define TILE_ELEMS (BM * STRIDE)         // 17408
#define TILE_BYTES (TILE_ELEMS * 2)      // 34816
#define SMEM_SZ (3 * TILE_BYTES)         // B + A0 + A1 = 104448

// Scratch (device globals — no allocation allowed)
__device__ __nv_bfloat16 g_nrep_bf16[TWO_N * ZD];
__device__ float         g_rowsum  [TWO_N];
__device__ float         g_pos     [TWO_N];
__device__ unsigned int  g_ticket;

// ---------------------------------------------------------------------------
// Kernel 1: normalize both rows of each positive pair (j, j+N) in one block;
// emit pre-scaled bf16 rows, fp32 positives, zero rowsums. 4096 blocks x 128.
// ---------------------------------------------------------------------------
__global__ void normalize_pos_kernel(const float* __restrict__ z1,
                                     const float* __restrict__ z2) {
    int j = blockIdx.x;                      // 0..4095
    int t = threadIdx.x;
    float v = z1[(size_t)j * ZD + t];
    float p = z2[(size_t)j * ZD + t];
    float s0 = v * v, s1 = p * p, s2 = v * p;
    #pragma unroll
    for (int o = 16; o > 0; o >>= 1) {
        s0 += __shfl_xor_sync(0xFFFFFFFFu, s0, o);
        s1 += __shfl_xor_sync(0xFFFFFFFFu, s1, o);
        s2 += __shfl_xor_sync(0xFFFFFFFFu, s2, o);
    }
    __shared__ float ws[4][3];
    int lane = t & 31, wid = t >> 5;
    if (lane == 0) { ws[wid][0] = s0; ws[wid][1] = s1; ws[wid][2] = s2; }
    __syncthreads();
    float n0 = ws[0][0] + ws[1][0] + ws[2][0] + ws[3][0];
    float n1 = ws[0][1] + ws[1][1] + ws[2][1] + ws[3][1];
    float dp = ws[0][2] + ws[1][2] + ws[2][2] + ws[3][2];
    float invA = 1.0f / fmaxf(sqrtf(n0), 1e-8f);
    float invB = 1.0f / fmaxf(sqrtf(n1), 1e-8f);
    g_nrep_bf16[(size_t)j * ZD + t] =
        __float2bfloat16(v * (invA * SQRT_EXP_SCALE));
    g_nrep_bf16[(size_t)(j + TWO_N/2) * ZD + t] =
        __float2bfloat16(p * (invB * SQRT_EXP_SCALE));
    if (t == 0) {
        float pos = dp * invA * invB;
        g_pos[j] = pos;
        g_pos[j + TWO_N/2] = pos;
        g_rowsum[j] = 0.0f;
        g_rowsum[j + TWO_N/2] = 0.0f;
        if (j == 0) g_ticket = 0u;
    }
}

// ---------------------------------------------------------------------------
// cp.async a full 128x128 bf16 tile (row strip rowBase) into padded smem
// ---------------------------------------------------------------------------
__device__ __forceinline__ void load_tile(__nv_bfloat16* dst, int rowBase, int tid) {
    #pragma unroll
    for (int it = 0; it < 4; it++) {
        int i2 = it * 512 + tid;          // 2048 16B-chunks per tile
        int rr = i2 >> 4, c = i2 & 15;
        uint32_t d = (uint32_t)__cvta_generic_to_shared(dst + rr * STRIDE + c * 8);
        const void* g = g_nrep_bf16 + (size_t)(rowBase + rr) * ZD + c * 8;
        asm volatile("cp.async.cg.shared.global [%0], [%1], 16;" :: "r"(d), "l"(g));
    }
}

// ---------------------------------------------------------------------------
// Per-tile epilogue (DIAG templated): ex2 of acc (scale pre-folded), optional
// self-diag mask; per-tile ROW flush (rows change every tile); column sums
// accumulate into persistent colacc registers (off-diag only — the diag tile's
// row sums already cover its column contributions).
// ---------------------------------------------------------------------------
template<bool DIAG>
__device__ __forceinline__ void epilogue(float (&acc)[2][4][4], float (&colacc)[8],
                                         int rowBase, int colBase,
                                         int wm, int wn, int lane) {
    int g = lane >> 2, t = lane & 3;

    #pragma unroll
    for (int mt = 0; mt < 2; mt++) {
        #pragma unroll
        for (int half = 0; half < 2; half++) {
            int i = rowBase + wm * 32 + mt * 16 + half * 8 + g;
            float s = 0.0f;
            #pragma unroll
            for (int nt = 0; nt < 4; nt++) {
                #pragma unroll
                for (int e = 0; e < 2; e++) {
                    float ex;
                    asm("ex2.approx.f32 %0, %1;" : "=f"(ex)
                        : "f"(acc[mt][nt][half * 2 + e]));
                    if (DIAG) {
                        int j = colBase + wn * 32 + t * 2 + nt * 8 + e;
                        if (i == j) ex = 0.0f;
                    }
                    s += ex;
                    if (!DIAG) colacc[nt * 2 + e] += ex;
                }
            }
            // row flush: reduce over t (lanes xor 1,2), lane t==0 commits
            s += __shfl_xor_sync(0xFFFFFFFFu, s, 1);
            s += __shfl_xor_sync(0xFFFFFFFFu, s, 2);
            if (t == 0) atomicAdd(&g_rowsum[i], s);
        }
    }
}

// Flush accumulated column sums for column strip colBase, then zero them.
__device__ __forceinline__ void flush_colacc(float (&colacc)[8], int colBase,
                                             int wn, int lane) {
    int g = lane >> 2, t = lane & 3;
    #pragma unroll
    for (int c = 0; c < 8; c++) {
        float v = colacc[c];
        v += __shfl_xor_sync(0xFFFFFFFFu, v, 4);
        v += __shfl_xor_sync(0xFFFFFFFFu, v, 8);
        v += __shfl_xor_sync(0xFFFFFFFFu, v, 16);
        colacc[c] = v;
    }
    if (g == 0) {
        int jbase = colBase + wn * 32 + t * 2;
        #pragma unroll
        for (int c = 0; c < 8; c++) {
            int j = jbase + (c >> 1) * 8 + (c & 1);
            atomicAdd(&g_rowsum[j], colacc[c]);
        }
    }
    #pragma unroll
    for (int c = 0; c < 8; c++) colacc[c] = 0.0f;
}

// ---------------------------------------------------------------------------
// Kernel 2: PERSISTENT fused sim GEMM, COLUMN-MAJOR triangle walk.
// Each CTA owns a contiguous chunk of tiles ordered column-major (tx fixed,
// ty = 0..tx). B (= column strip) loaded once per column; A (row strip)
// double-buffered and prefetched every tile. Column sums ride in registers
// across the chunk, flushed at each diag tile / chunk end.
// 512 threads = 16 warps (4m x 4n), 32x32 warp tile.
// ---------------------------------------------------------------------------
__global__ void __launch_bounds__(512, 2) simgemm_kernel(float* __restrict__ out) {
    extern __shared__ __nv_bfloat16 smem[];
    __nv_bfloat16* sB = smem;                   // column strip (fixed per column)
    __nv_bfloat16* sA = smem + TILE_ELEMS;      // A0; A1 at +TILE_ELEMS

    int tid = threadIdx.x;
    int wid = tid >> 5, lane = tid & 31;

    // Contiguous chunk in column-major triangle order
    const int base = NUM_TILES / NUM_CTAS;      // 6
    const int rem  = NUM_TILES % NUM_CTAS;      // 256
    int bidx = blockIdx.x;
    int start = bidx * base + (bidx < rem ? bidx : rem);
    int count = base + (bidx < rem ? 1 : 0);

    // Decode start -> (tx, ty): column tx holds tiles ty in [0, tx]
    int tx = (int)((sqrtf(8.0f * (float)start + 1.0f) - 1.0f) * 0.5f);
    while (tx * (tx + 1) / 2 > start) tx--;
    while ((tx + 1) * (tx + 2) / 2 <= start) tx++;
    int ty = start - tx * (tx + 1) / 2;

    // Initial loads: B(tx) + A(ty) as one group
    load_tile(sB, tx * BN, tid);
    load_tile(sA, ty * BM, tid);
    asm volatile("cp.async.commit_group;" ::: "memory");

    int wm = wid & 3;        // warp row (4)
    int wn = wid >> 2;       // warp col (4)

    // ldmatrix base addresses (per lane); A offset adds (t&1)*TILE_BYTES
    uint32_t aAddr[2];
    #pragma unroll
    for (int mt = 0; mt < 2; mt++) {
        int row = wm * 32 + mt * 16 + (lane & 15);
        int k = (lane >> 4) * 8;
        aAddr[mt] = (uint32_t)__cvta_generic_to_shared(sA + row * STRIDE + k);
    }
    uint32_t bAddr[2];
    #pragma unroll
    for (int ntp = 0; ntp < 2; ntp++) {
        int n = wn * 32 + ntp * 16 + ((lane >> 4) & 1) * 8 + (lane & 7);
        int k = ((lane >> 3) & 1) * 8;
        bAddr[ntp] = (uint32_t)__cvta_generic_to_shared(sB + n * STRIDE + k);
    }

    float colacc[8];
    #pragma unroll
    for (int c = 0; c < 8; c++) colacc[c] = 0.0f;

    #pragma unroll 1
    for (int t = 0; t < count; t++) {
        uint32_t aOff = (uint32_t)(t & 1) * TILE_BYTES;
        int nty = ty + 1, ntx = tx;
        if (nty > tx) { ntx = tx + 1; nty = 0; }
        bool more = (t + 1 < count);

        // Wait for this tile's data (prefetched -> usually free)
        asm volatile("cp.async.wait_group 0;" ::: "memory");
        __syncthreads();

        // Same column: prefetch next A into the alternate buffer (overlaps)
        if (more && ntx == tx) {
            load_tile(sA + ((t + 1) & 1) * TILE_ELEMS, nty * BM, tid);
            asm volatile("cp.async.commit_group;" ::: "memory");
        }

        float acc[2][4][4];
        #pragma unroll
        for (int mt = 0; mt < 2; mt++)
            #pragma unroll
            for (int nt = 0; nt < 4; nt++)
                #pragma unroll
                for (int e = 0; e < 4; e++) acc[mt][nt][e] = 0.0f;

        // ---- Mainloop: 8 k-steps of k16
        #pragma unroll
        for (int ks = 0; ks < 8; ks++) {
            uint32_t a[2][4];
            #pragma unroll
            for (int mt = 0; mt < 2; mt++)
                asm volatile("ldmatrix.sync.aligned.m8n8.x4.shared.b16 {%0,%1,%2,%3}, [%4];"
                    : "=r"(a[mt][0]), "=r"(a[mt][1]), "=r"(a[mt][2]), "=r"(a[mt][3])
                    : "r"(aAddr[mt] + aOff + ks * 32));
            uint32_t b[4][2];
            #pragma unroll
            for (int ntp = 0; ntp < 2; ntp++)
                asm volatile("ldmatrix.sync.aligned.m8n8.x4.shared.b16 {%0,%1,%2,%3}, [%4];"
                    : "=r"(b[2*ntp][0]), "=r"(b[2*ntp][1]),
                      "=r"(b[2*ntp+1][0]), "=r"(b[2*ntp+1][1])
                    : "r"(bAddr[ntp] + ks * 32));
            #pragma unroll
            for (int mt = 0; mt < 2; mt++)
                #pragma unroll
                for (int nt = 0; nt < 4; nt++)
                    asm volatile(
                        "mma.sync.aligned.m16n8k16.row.col.f32.bf16.bf16.f32 "
                        "{%0,%1,%2,%3}, {%4,%5,%6,%7}, {%8,%9}, {%0,%1,%2,%3};"
                        : "+f"(acc[mt][nt][0]), "+f"(acc[mt][nt][1]),
                          "+f"(acc[mt][nt][2]), "+f"(acc[mt][nt][3])
                        : "r"(a[mt][0]), "r"(a[mt][1]), "r"(a[mt][2]), "r"(a[mt][3]),
                          "r"(b[nt][0]), "r"(b[nt][1]));
        }

        if (ty == tx) {
            epilogue<true >(acc, colacc, ty * BM, tx * BN, wm, wn, lane);
            flush_colacc(colacc, tx * BN, wn, lane);   // column complete
        } else {
            epilogue<false>(acc, colacc, ty * BM, tx * BN, wm, wn, lane);
        }

        // Column transition: reload B (+A) — needs all warps done reading sB
        if (more && ntx != tx) {
            __syncthreads();
            load_tile(sB, ntx * BN, tid);
            load_tile(sA + ((t + 1) & 1) * TILE_ELEMS, nty * BM, tid);
            asm volatile("cp.async.commit_group;" ::: "memory");
        }
        ty = nty; tx = ntx;
    }

    // Flush any partial column left at chunk end (zeros if already flushed)
    flush_colacc(colacc, (ty == 0 ? tx - 1 : tx) * BN, wn, lane);

    // ---- Ticket: last CTA computes the scalar loss (fast log2)
    __shared__ bool is_last;
    __syncthreads();
    if (tid == 0) {
        __threadfence();
        unsigned int tk = atomicInc(&g_ticket, 0xFFFFFFFFu);
        is_last = (tk == (unsigned int)(gridDim.x - 1));
    }
    __syncthreads();
    if (is_last) {
        __threadfence();
        float acc2 = 0.0f;
        #pragma unroll 4
        for (int i = tid; i < TWO_N; i += 512)
            acc2 += __log2f(__ldcg(&g_rowsum[i])) * LN2F - g_pos[i] * INV_T;
        #pragma unroll
        for (int o = 16; o > 0; o >>= 1)
            acc2 += __shfl_xor_sync(0xFFFFFFFFu, acc2, o);
        __shared__ float sred[16];
        if ((tid & 31) == 0) sred[tid >> 5] = acc2;
        __syncthreads();
        if (tid == 0) {
            float tot = 0.0f;
            #pragma unroll
            for (int w = 0; w < 16; w++) tot += sred[w];
            out[0] = tot * (1.0f / (float)TWO_N);
        }
    }
}

// ---------------------------------------------------------------------------
extern "C" void kernel_launch(void* const* d_in, const int* in_sizes, int n_in,
                              void* d_out, int out_size) {
    const float* z1 = (const float*)d_in[0];
    const float* z2 = (const float*)d_in[1];

    cudaFuncSetAttribute(simgemm_kernel,
                         cudaFuncAttributeMaxDynamicSharedMemorySize, SMEM_SZ);

    normalize_pos_kernel<<<TWO_N / 2, 128>>>(z1, z2);
    simgemm_kernel<<<NUM_CTAS, 512, SMEM_SZ>>>((float*)d_out);
}